// round 14
// baseline (speedup 1.0000x reference)
#include <cuda_runtime.h>
#include <cuda_fp16.h>
#include <math.h>
#include <stdint.h>

#define E_  8
#define H_  2048
#define I_  1024
#define I2_ 2048
#define L_  4
#define R_  16
#define T_  4096
#define P_  8192

#define KT1 2112     // H + L*R  (33 * 64)
#define KT2 1088     // I + L*R  (17 * 64)

// -------- scratch (device globals; allocation-free) --------
__device__ __half g_Xh[(size_t)T_*H_];          // fp16 x, one row per token
__device__ __half g_U1[(size_t)P_*64];          // per-pair LoRA ext for GEMM1
__device__ __half g_B1[(size_t)E_*I2_*KT1];
__device__ __half g_A2[(size_t)P_*KT2];         // act (cw-scaled) + V ext
__device__ __half g_B2[(size_t)E_*H_*KT2];
__device__ __half g_Dh[(size_t)P_*H_];          // cw-scaled down output, fp16
__device__ __half g_GAh[(size_t)L_*E_*R_*H_];   // fp16 gu_lora_a
__device__ __half g_DAh[(size_t)L_*E_*R_*I_];   // fp16 down_lora_a
__device__ int   g_list[P_], g_pos[P_], g_off[E_+1];

// -------- helpers --------
__device__ __forceinline__ uint32_t smem_u32(const void* p) {
    uint32_t a;
    asm("{ .reg .u64 t; cvta.to.shared.u64 t, %1; cvt.u32.u64 %0, t; }" : "=r"(a) : "l"(p));
    return a;
}
__device__ __forceinline__ uint32_t pk2(__half a, __half b) {
    __half2 t = __halves2half2(a, b);
    return *reinterpret_cast<uint32_t*>(&t);
}
__device__ __forceinline__ uint4 cvt8(float4 v0, float4 v1) {
    uint4 u;
    u.x = pk2(__float2half(v0.x), __float2half(v0.y));
    u.y = pk2(__float2half(v0.z), __float2half(v0.w));
    u.z = pk2(__float2half(v1.x), __float2half(v1.y));
    u.w = pk2(__float2half(v1.z), __float2half(v1.w));
    return u;
}
__device__ __forceinline__ void cp16(uint32_t dst, const void* src) {
    asm volatile("cp.async.cg.shared.global [%0], [%1], 16;" :: "r"(dst), "l"(src));
}
#define CP_COMMIT() asm volatile("cp.async.commit_group;" ::: "memory")
#define CP_WAIT1()  asm volatile("cp.async.wait_group 1;" ::: "memory")
#define CP_WAIT0()  asm volatile("cp.async.wait_group 0;" ::: "memory")

__device__ __forceinline__ void ldsm4(uint32_t* r, uint32_t addr) {
    asm volatile("ldmatrix.sync.aligned.m8n8.x4.shared.b16 {%0,%1,%2,%3}, [%4];"
        : "=r"(r[0]), "=r"(r[1]), "=r"(r[2]), "=r"(r[3]) : "r"(addr));
}
__device__ __forceinline__ void mma_f16(float* d, const uint32_t* a, const uint32_t* b) {
    asm volatile(
        "mma.sync.aligned.m16n8k16.row.col.f32.f16.f16.f32 "
        "{%0,%1,%2,%3}, {%4,%5,%6,%7}, {%8,%9}, {%0,%1,%2,%3};"
        : "+f"(d[0]), "+f"(d[1]), "+f"(d[2]), "+f"(d[3])
        : "r"(a[0]), "r"(a[1]), "r"(a[2]), "r"(a[3]), "r"(b[0]), "r"(b[1]));
}
// [rows x 64 fp16] tile, row stride 128B, 8x 16B chunks/row
__device__ __forceinline__ uint32_t swz64(int r, int c) {
    return (uint32_t)(r * 128 + ((c ^ (r & 7)) << 4));
}
__device__ __forceinline__ float wred(float v) {
    #pragma unroll
    for (int o = 16; o; o >>= 1) v += __shfl_down_sync(0xffffffffu, v, o);
    return v;
}

// ============================================================
// routing: sort pairs by (expert, lora)  (1024 threads)
// ============================================================
__global__ void k_route(const int* __restrict__ topk_ids,
                        const int* __restrict__ lora_idx) {
    __shared__ int cnt[E_*L_], cur[E_*L_];
    int tid = threadIdx.x;
    if (tid < E_*L_) cnt[tid] = 0;
    __syncthreads();
    for (int p = tid; p < P_; p += blockDim.x)
        atomicAdd(&cnt[topk_ids[p]*L_ + lora_idx[p>>1]], 1);
    __syncthreads();
    if (tid == 0) {
        int acc = 0;
        for (int b = 0; b < E_*L_; b++) {
            if ((b & (L_-1)) == 0) g_off[b/L_] = acc;
            cur[b] = acc; acc += cnt[b];
        }
        g_off[E_] = acc;
    }
    __syncthreads();
    for (int p = tid; p < P_; p += blockDim.x) {
        int key = topk_ids[p]*L_ + lora_idx[p>>1];
        int pos = atomicAdd(&cur[key], 1);
        g_list[pos] = p;
        g_pos[p]    = pos;
    }
}

// ============================================================
// conva: gu_a, d_a -> fp16 tables
// ============================================================
__global__ __launch_bounds__(256) void k_conva(
    const float* __restrict__ gu_a, const float* __restrict__ d_a) {
    int bid = blockIdx.x, tid = threadIdx.x;
    if (bid < 512) {
        size_t base = ((size_t)bid * 256 + tid) * 8;
        const float4* s = (const float4*)(gu_a + base);
        *(uint4*)(g_GAh + base) = cvt8(s[0], s[1]);
    } else {
        size_t base = ((size_t)(bid - 512) * 256 + tid) * 8;
        const float4* s = (const float4*)(d_a + base);
        *(uint4*)(g_DAh + base) = cvt8(s[0], s[1]);
    }
}

// ============================================================
// prep1: 4 sorted pairs per block
// ============================================================
__global__ __launch_bounds__(256) void k_prep1(
    const float* __restrict__ x,
    const int* __restrict__ topk_ids, const int* __restrict__ lora_idx) {
    __shared__ float sx[4][2048];
    __shared__ int sle[4], sp[4];
    int tid = threadIdx.x;
    int s0 = blockIdx.x * 4;
    if (tid < 4) {
        int p = g_list[s0 + tid];
        sp[tid] = p;
        sle[tid] = lora_idx[p >> 1] * E_ + topk_ids[p];
    }
    __syncthreads();
    #pragma unroll
    for (int j = 0; j < 4; j++) {
        int p = sp[j], t = p >> 1;
        const float4* x4 = (const float4*)(x + (size_t)t * H_);
        float4 v0 = x4[tid*2], v1 = x4[tid*2+1];
        *(float4*)&sx[j][tid*8]     = v0;
        *(float4*)&sx[j][tid*8 + 4] = v1;
        if ((p & 1) == 0)
            *(uint4*)(g_Xh + (size_t)t * H_ + tid*8) = cvt8(v0, v1);
    }
    {
        int j = tid >> 6, c = tid & 63;
        g_U1[(size_t)(s0 + j) * 64 + c] = __float2half(0.f);
    }
    __syncthreads();

    int lane = tid & 31, w = tid >> 5;
    bool uni = (sle[0] == sle[1]) && (sle[1] == sle[2]) && (sle[2] == sle[3]);
    if (uni) {
        const __half2* ga = (const __half2*)(g_GAh + ((size_t)sle[0]*R_ + w) * H_);
        const __half2* gb = ga + 8 * (H_/2);
        float sa[4] = {0,0,0,0}, sb[4] = {0,0,0,0};
        for (int it = lane; it < H_/2; it += 32) {
            float2 a2 = __half22float2(ga[it]);
            float2 b2 = __half22float2(gb[it]);
            #pragma unroll
            for (int j = 0; j < 4; j++) {
                float x0 = sx[j][2*it], x1 = sx[j][2*it + 1];
                sa[j] += x0*a2.x + x1*a2.y;
                sb[j] += x0*b2.x + x1*b2.y;
            }
        }
        #pragma unroll
        for (int j = 0; j < 4; j++) {
            float ra = wred(sa[j]), rb = wred(sb[j]);
            if (lane == 0) {
                int l = sle[j] / E_;
                __half* ru = g_U1 + (size_t)(s0 + j) * 64;
                ru[l*R_ + w]     = __float2half(ra);
                ru[l*R_ + w + 8] = __float2half(rb);
            }
        }
    } else {
        for (int j = 0; j < 4; j++) {
            const __half2* ga = (const __half2*)(g_GAh + ((size_t)sle[j]*R_ + w) * H_);
            const __half2* gb = ga + 8 * (H_/2);
            float sa = 0.f, sb = 0.f;
            for (int it = lane; it < H_/2; it += 32) {
                float2 a2 = __half22float2(ga[it]);
                float2 b2 = __half22float2(gb[it]);
                float x0 = sx[j][2*it], x1 = sx[j][2*it + 1];
                sa += x0*a2.x + x1*a2.y;
                sb += x0*b2.x + x1*b2.y;
            }
            sa = wred(sa); sb = wred(sb);
            if (lane == 0) {
                int l = sle[j] / E_;
                __half* ru = g_U1 + (size_t)(s0 + j) * 64;
                ru[l*R_ + w]     = __float2half(sa);
                ru[l*R_ + w + 8] = __float2half(sb);
            }
        }
    }
}

// ============================================================
// weight conversion (fp16); convw1 takes an expert base for splitting
// ============================================================
__global__ __launch_bounds__(256) void k_convw1(
    const float* __restrict__ w13, const float* __restrict__ gu_b, int ebase) {
    int rc = ebase * I2_ + blockIdx.x;
    int tid = threadIdx.x;
    int e = rc >> 11, c = rc & 2047;
    const float4* src = (const float4*)(w13 + (size_t)rc * H_);
    __half* bh = g_B1 + (size_t)rc * KT1;
    *(uint4*)(bh + tid*8) = cvt8(src[tid*2], src[tid*2+1]);
    if (tid < L_*R_) {
        int l = tid >> 4, r = tid & 15;
        bh[H_+tid] = __float2half(gu_b[(((size_t)l*E_ + e)*I2_ + c)*R_ + r]);
    }
}

__global__ __launch_bounds__(256) void k_convw2(
    const float* __restrict__ w2, const float* __restrict__ d_b) {
    int rc = blockIdx.x, tid = threadIdx.x;
    int e = rc >> 11, c = rc & 2047;
    const float4* src = (const float4*)(w2 + (size_t)rc * I_);
    __half* bh = g_B2 + (size_t)rc * KT2;
    float4 v0 = src[tid];
    *(uint2*)(bh + tid*4) = make_uint2(
        pk2(__float2half(v0.x), __float2half(v0.y)),
        pk2(__float2half(v0.z), __float2half(v0.w)));
    if (tid < L_*R_) {
        int l = tid >> 4, r = tid & 15;
        bh[I_+tid] = __float2half(d_b[(((size_t)l*E_ + e)*H_ + c)*R_ + r]);
    }
}

// ============================================================
// prep2: 4 pairs per block
// ============================================================
__global__ __launch_bounds__(256) void k_prep2(
    const int* __restrict__ topk_ids, const int* __restrict__ lora_idx) {
    __shared__ __half2 sac[4][512];
    __shared__ int sle[4];
    int tid = threadIdx.x;
    int s0 = blockIdx.x * 4;
    if (tid < 4) {
        int p = g_list[s0 + tid];
        sle[tid] = lora_idx[p >> 1] * E_ + topk_ids[p];
    }
    __syncthreads();
    #pragma unroll
    for (int j = 0; j < 4; j += 2) {
        int row = j + (tid >> 7);
        int c   = tid & 127;
        const uint4 v = *(const uint4*)(g_A2 + (size_t)(s0 + row) * KT2 + c*8);
        *(uint4*)&sac[row][c*4] = v;
    }
    {
        int j = tid >> 6, c = tid & 63;
        g_A2[(size_t)(s0 + j) * KT2 + I_ + c] = __float2half(0.f);
    }
    __syncthreads();

    int lane = tid & 31, w = tid >> 5;
    bool uni = (sle[0] == sle[1]) && (sle[1] == sle[2]) && (sle[2] == sle[3]);
    if (uni) {
        const __half2* ga = (const __half2*)(g_DAh + ((size_t)sle[0]*R_ + w) * I_);
        const __half2* gb = ga + 8 * (I_/2);
        float sa[4] = {0,0,0,0}, sb[4] = {0,0,0,0};
        for (int it = lane; it < I_/2; it += 32) {
            float2 a2 = __half22float2(ga[it]);
            float2 b2 = __half22float2(gb[it]);
            #pragma unroll
            for (int j = 0; j < 4; j++) {
                float2 xv = __half22float2(sac[j][it]);
                sa[j] += xv.x*a2.x + xv.y*a2.y;
                sb[j] += xv.x*b2.x + xv.y*b2.y;
            }
        }
        #pragma unroll
        for (int j = 0; j < 4; j++) {
            float ra = wred(sa[j]), rb = wred(sb[j]);
            if (lane == 0) {
                int l = sle[j] / E_;
                __half* ru = g_A2 + (size_t)(s0 + j) * KT2 + I_;
                ru[l*R_ + w]     = __float2half(ra);
                ru[l*R_ + w + 8] = __float2half(rb);
            }
        }
    } else {
        for (int j = 0; j < 4; j++) {
            const __half2* ga = (const __half2*)(g_DAh + ((size_t)sle[j]*R_ + w) * I_);
            const __half2* gb = ga + 8 * (I_/2);
            float sa = 0.f, sb = 0.f;
            for (int it = lane; it < I_/2; it += 32) {
                float2 a2 = __half22float2(ga[it]);
                float2 b2 = __half22float2(gb[it]);
                float2 xv = __half22float2(sac[j][it]);
                sa += xv.x*a2.x + xv.y*a2.y;
                sb += xv.x*b2.x + xv.y*b2.y;
            }
            sa = wred(sa); sb = wred(sb);
            if (lane == 0) {
                int l = sle[j] / E_;
                __half* ru = g_A2 + (size_t)(s0 + j) * KT2 + I_;
                ru[l*R_ + w]     = __float2half(sa);
                ru[l*R_ + w + 8] = __float2half(sb);
            }
        }
    }
}

// ============================================================
// mma.sync GEMM: CTA 128x256, 256 threads / 8 warps (64x64 each).
// Pure fp16, K chunk 64, 3 stages x 48KB. ezoff = expert base.
// ============================================================
#define STAGE 49152
#define SMEMB (3*STAGE)   // 147456 >= exchange 133120

template<int GEMM>
__global__ __launch_bounds__(256, 1) void k_gemm_mma(const float* __restrict__ tw, int ezoff) {
    constexpr int KTOT = (GEMM == 1) ? KT1 : KT2;
    constexpr int NK   = KTOT / 64;
    constexpr int NKX  = NK - 1;
    const __half* Bb = (GEMM == 1) ? g_B1 : g_B2;

    int e   = blockIdx.z + ezoff;
    int off = g_off[e];
    int cnt = g_off[e+1] - off;
    int m0  = blockIdx.y * 128;
    if (m0 >= cnt) return;

    extern __shared__ char smem_raw[];
    uint32_t sbase = smem_u32(smem_raw);

    int tid = threadIdx.x;
    int lane = tid & 31, wid = tid >> 5;
    int wm = wid >> 2, wn = wid & 3;

    uint32_t aX[4], aU[4], sAo[4];
    #pragma unroll
    for (int j = 0; j < 4; j++) {
        int id = tid + 256*j, r = id >> 3, c = id & 7;
        int rA = m0 + r; if (rA > cnt-1) rA = cnt-1;
        int srow = off + rA;
        if (GEMM == 1) {
            int p = g_list[srow];
            aX[j] = (uint32_t)(p >> 1) * H_ + c*8;
            aU[j] = (uint32_t)srow * 64 + c*8;
        } else {
            aX[j] = (uint32_t)srow * KT2 + c*8;
        }
        sAo[j] = swz64(r, c);
    }
    uint32_t bO[8], sBo[8];
    #pragma unroll
    for (int j = 0; j < 8; j++) {
        int id = tid + 256*j, n = id >> 3, c = id & 7;
        int colB;
        if (GEMM == 1) colB = blockIdx.x*128 + (n & 127) + ((n >> 7) * I_);
        else           colB = blockIdx.x*256 + n;
        bO[j] = ((uint32_t)e * 2048 + colB) * KTOT + c*8;
        sBo[j] = swz64(n, c);
    }

    auto issue = [&](int kt) {
        uint32_t st = sbase + (kt % 3) * STAGE;
        uint32_t kadd = (uint32_t)kt * 64;
        #pragma unroll
        for (int j = 0; j < 4; j++) {
            const __half* src;
            if (GEMM == 1) src = (kt < NKX) ? (g_Xh + aX[j] + kadd) : (g_U1 + aU[j]);
            else           src = g_A2 + aX[j] + kadd;
            cp16(st + sAo[j], src);
        }
        #pragma unroll
        for (int j = 0; j < 8; j++)
            cp16(st + 16384 + sBo[j], Bb + bO[j] + kadd);
    };

    int aRow[4], bRow[4];
    #pragma unroll
    for (int i = 0; i < 4; i++) aRow[i] = wm*64 + i*16 + (lane & 15);
    int aC = (lane >> 4) & 1;
    #pragma unroll
    for (int g = 0; g < 4; g++) bRow[g] = wn*64 + g*16 + (lane & 7) + ((lane & 16) ? 8 : 0);
    int bC = (lane >> 3) & 1;

    float acc[4][8][4];
    #pragma unroll
    for (int i = 0; i < 4; i++)
        #pragma unroll
        for (int j = 0; j < 8; j++)
            #pragma unroll
            for (int q = 0; q < 4; q++) acc[i][j][q] = 0.f;

    issue(0); CP_COMMIT();
    issue(1); CP_COMMIT();

    for (int kt = 0; kt < NK; kt++) {
        CP_WAIT1();
        __syncthreads();
        if (kt + 2 < NK) issue(kt + 2);
        CP_COMMIT();

        uint32_t st = sbase + (kt % 3) * STAGE;
        #pragma unroll
        for (int h = 0; h < 4; h++) {
            uint32_t ar[4][4], br[4][4];
            #pragma unroll
            for (int i = 0; i < 4; i++)
                ldsm4(ar[i], st + swz64(aRow[i], 2*h + aC));
            #pragma unroll
            for (int g = 0; g < 4; g++)
                ldsm4(br[g], st + 16384 + swz64(bRow[g], 2*h + bC));
            #pragma unroll
            for (int i = 0; i < 4; i++)
                #pragma unroll
                for (int j = 0; j < 8; j++)
                    mma_f16(acc[i][j], ar[i], &br[j>>1][(j&1)*2]);
        }
    }
    CP_WAIT0();
    __syncthreads();

    if constexpr (GEMM == 1) {
        float* ex = reinterpret_cast<float*>(smem_raw);
        #pragma unroll
        for (int i = 0; i < 4; i++)
            #pragma unroll
            for (int j = 0; j < 8; j++) {
                int r0 = wm*64 + i*16 + (lane >> 2);
                int c  = wn*64 + j*8 + (lane & 3)*2;
                ex[r0*260 + c]       = acc[i][j][0];
                ex[r0*260 + c + 1]   = acc[i][j][1];
                ex[(r0+8)*260 + c]   = acc[i][j][2];
                ex[(r0+8)*260 + c+1] = acc[i][j][3];
            }
        __syncthreads();
        int m = tid >> 1, half = tid & 1;
        if (m0 + m < cnt) {
            size_t srow = (size_t)(off + m0 + m);
            float cw = tw[g_list[srow]];
            __half* da = g_A2 + srow * KT2 + blockIdx.x*128 + half*64;
            const float* gr = ex + m*260 + half*64;
            #pragma unroll
            for (int q = 0; q < 8; q++) {
                uint32_t hw[4];
                #pragma unroll
                for (int u = 0; u < 4; u++) {
                    float g0 = gr[q*8 + u*2], g1 = gr[q*8 + u*2 + 1];
                    float u0 = gr[128 + q*8 + u*2], u1 = gr[128 + q*8 + u*2 + 1];
                    float a0 = cw * u0 * g0 / (1.f + expf(-g0));
                    float a1 = cw * u1 * g1 / (1.f + expf(-g1));
                    hw[u] = pk2(__float2half(a0), __float2half(a1));
                }
                *(uint4*)(da + q*8) = make_uint4(hw[0], hw[1], hw[2], hw[3]);
            }
        }
    } else {
        int c0 = blockIdx.x * 256;
        #pragma unroll
        for (int i = 0; i < 4; i++) {
            int r0 = m0 + wm*64 + i*16 + (lane >> 2);
            #pragma unroll
            for (int j = 0; j < 8; j++) {
                int c = c0 + wn*64 + j*8 + (lane & 3)*2;
                if (r0 < cnt)
                    *(uint32_t*)(g_Dh + (size_t)(off + r0) * H_ + c) =
                        pk2(__float2half(acc[i][j][0]), __float2half(acc[i][j][1]));
                if (r0 + 8 < cnt)
                    *(uint32_t*)(g_Dh + (size_t)(off + r0 + 8) * H_ + c) =
                        pk2(__float2half(acc[i][j][2]), __float2half(acc[i][j][3]));
            }
        }
    }
}

// ============================================================
// combine: out[t] = Dh[pos(t,0)] + Dh[pos(t,1)]
// ============================================================
__global__ __launch_bounds__(256) void k_combine(float* __restrict__ out) {
    int idx = blockIdx.x * 256 + threadIdx.x;
    int t = idx >> 8, q = idx & 255;
    const uint4 u0 = *(const uint4*)(g_Dh + (size_t)g_pos[2*t]   * H_ + q*8);
    const uint4 u1 = *(const uint4*)(g_Dh + (size_t)g_pos[2*t+1] * H_ + q*8);
    const __half2* h0 = (const __half2*)&u0;
    const __half2* h1 = (const __half2*)&u1;
    float4 o0, o1;
    {
        float2 a = __half22float2(h0[0]), b = __half22float2(h1[0]);
        o0.x = a.x + b.x; o0.y = a.y + b.y;
        a = __half22float2(h0[1]); b = __half22float2(h1[1]);
        o0.z = a.x + b.x; o0.w = a.y + b.y;
        a = __half22float2(h0[2]); b = __half22float2(h1[2]);
        o1.x = a.x + b.x; o1.y = a.y + b.y;
        a = __half22float2(h0[3]); b = __half22float2(h1[3]);
        o1.z = a.x + b.x; o1.w = a.y + b.y;
    }
    float4* dst = (float4*)(out + (size_t)t * H_ + q*8);
    dst[0] = o0; dst[1] = o1;
}

// ============================================================
extern "C" void kernel_launch(void* const* d_in, const int* in_sizes, int n_in,
                              void* d_out, int out_size) {
    const float* x    = (const float*)d_in[0];
    const float* tw   = (const float*)d_in[1];
    const float* w13  = (const float*)d_in[2];
    const float* w2   = (const float*)d_in[3];
    const float* gu_a = (const float*)d_in[4];
    const float* gu_b = (const float*)d_in[5];
    const float* da   = (const float*)d_in[6];
    const float* db   = (const float*)d_in[7];
    const int*   ids  = (const int*)d_in[8];
    const int*   lidx = (const int*)d_in[9];
    float* out = (float*)d_out;

    static cudaStream_t s1 = nullptr;
    static cudaEvent_t evFork = nullptr, evA = nullptr;
    static cudaEvent_t evW1a = nullptr, evW1b = nullptr, evW2 = nullptr;
    if (!s1) {
        cudaStreamCreate(&s1);
        cudaEventCreateWithFlags(&evFork, cudaEventDisableTiming);
        cudaEventCreateWithFlags(&evA,    cudaEventDisableTiming);
        cudaEventCreateWithFlags(&evW1a,  cudaEventDisableTiming);
        cudaEventCreateWithFlags(&evW1b,  cudaEventDisableTiming);
        cudaEventCreateWithFlags(&evW2,   cudaEventDisableTiming);
        cudaFuncSetAttribute(k_gemm_mma<1>, cudaFuncAttributeMaxDynamicSharedMemorySize, SMEMB);
        cudaFuncSetAttribute(k_gemm_mma<2>, cudaFuncAttributeMaxDynamicSharedMemorySize, SMEMB);
    }

    // side stream: LoRA-A tables, then weight conversions (split convw1)
    cudaEventRecord(evFork, 0);
    cudaStreamWaitEvent(s1, evFork, 0);
    k_conva  <<<768, 256, 0, s1>>>(gu_a, da);
    cudaEventRecord(evA, s1);
    k_convw1 <<<4*I2_, 256, 0, s1>>>(w13, gu_b, 0);   // experts 0-3
    cudaEventRecord(evW1a, s1);
    k_convw1 <<<4*I2_, 256, 0, s1>>>(w13, gu_b, 4);   // experts 4-7
    cudaEventRecord(evW1b, s1);
    k_convw2 <<<E_*H_,  256, 0, s1>>>(w2, db);
    cudaEventRecord(evW2, s1);

    // main chain
    k_route  <<<1, 1024>>>(ids, lidx);
    cudaStreamWaitEvent(0, evA, 0);
    k_prep1  <<<P_/4, 256>>>(x, ids, lidx);
    cudaStreamWaitEvent(0, evW1a, 0);
    k_gemm_mma<1><<<dim3(8, 64, 4), 256, SMEMB>>>(tw, 0);   // experts 0-3
    cudaStreamWaitEvent(0, evW1b, 0);
    k_gemm_mma<1><<<dim3(8, 64, 4), 256, SMEMB>>>(tw, 4);   // experts 4-7
    k_prep2  <<<P_/4, 256>>>(ids, lidx);
    cudaStreamWaitEvent(0, evW2, 0);
    k_gemm_mma<2><<<dim3(8, 64, E_), 256, SMEMB>>>(tw, 0);
    k_combine<<<(T_*H_/8)/256, 256>>>(out);
}

// round 15
// speedup vs baseline: 1.0734x; 1.0734x over previous
#include <cuda_runtime.h>
#include <cuda_fp16.h>
#include <math.h>
#include <stdint.h>

#define E_  8
#define H_  2048
#define I_  1024
#define I2_ 2048
#define L_  4
#define R_  16
#define T_  4096
#define P_  8192

#define KT1 2112     // H + L*R  (33 * 64)
#define KT2 1088     // I + L*R  (17 * 64)

// -------- scratch (device globals; allocation-free) --------
__device__ __half g_Xh[(size_t)T_*H_];
__device__ __half g_U1[(size_t)P_*64];
__device__ __half g_B1[(size_t)E_*I2_*KT1];
__device__ __half g_A2[(size_t)P_*KT2];
__device__ __half g_B2[(size_t)E_*H_*KT2];
__device__ __half g_Dh[(size_t)P_*H_];
__device__ __half g_GAh[(size_t)L_*E_*R_*H_];
__device__ __half g_DAh[(size_t)L_*E_*R_*I_];
__device__ int   g_list[P_], g_pos[P_], g_off[E_+1];

// -------- helpers --------
__device__ __forceinline__ uint32_t smem_u32(const void* p) {
    uint32_t a;
    asm("{ .reg .u64 t; cvta.to.shared.u64 t, %1; cvt.u32.u64 %0, t; }" : "=r"(a) : "l"(p));
    return a;
}
__device__ __forceinline__ uint32_t pk2(__half a, __half b) {
    __half2 t = __halves2half2(a, b);
    return *reinterpret_cast<uint32_t*>(&t);
}
__device__ __forceinline__ uint4 cvt8(float4 v0, float4 v1) {
    uint4 u;
    u.x = pk2(__float2half(v0.x), __float2half(v0.y));
    u.y = pk2(__float2half(v0.z), __float2half(v0.w));
    u.z = pk2(__float2half(v1.x), __float2half(v1.y));
    u.w = pk2(__float2half(v1.z), __float2half(v1.w));
    return u;
}
__device__ __forceinline__ void cp16(uint32_t dst, const void* src) {
    asm volatile("cp.async.cg.shared.global [%0], [%1], 16;" :: "r"(dst), "l"(src));
}
#define CP_COMMIT() asm volatile("cp.async.commit_group;" ::: "memory")
#define CP_WAIT1()  asm volatile("cp.async.wait_group 1;" ::: "memory")
#define CP_WAIT0()  asm volatile("cp.async.wait_group 0;" ::: "memory")

__device__ __forceinline__ void ldsm4(uint32_t* r, uint32_t addr) {
    asm volatile("ldmatrix.sync.aligned.m8n8.x4.shared.b16 {%0,%1,%2,%3}, [%4];"
        : "=r"(r[0]), "=r"(r[1]), "=r"(r[2]), "=r"(r[3]) : "r"(addr));
}
__device__ __forceinline__ void mma_f16(float* d, const uint32_t* a, const uint32_t* b) {
    asm volatile(
        "mma.sync.aligned.m16n8k16.row.col.f32.f16.f16.f32 "
        "{%0,%1,%2,%3}, {%4,%5,%6,%7}, {%8,%9}, {%0,%1,%2,%3};"
        : "+f"(d[0]), "+f"(d[1]), "+f"(d[2]), "+f"(d[3])
        : "r"(a[0]), "r"(a[1]), "r"(a[2]), "r"(a[3]), "r"(b[0]), "r"(b[1]));
}
// [rows x 64 fp16] tile, row stride 128B
__device__ __forceinline__ uint32_t swz64(int r, int c) {
    return (uint32_t)(r * 128 + ((c ^ (r & 7)) << 4));
}
__device__ __forceinline__ float wred(float v) {
    #pragma unroll
    for (int o = 16; o; o >>= 1) v += __shfl_down_sync(0xffffffffu, v, o);
    return v;
}

// ============================================================
// routing
// ============================================================
__global__ void k_route(const int* __restrict__ topk_ids,
                        const int* __restrict__ lora_idx) {
    __shared__ int cnt[E_*L_], cur[E_*L_];
    int tid = threadIdx.x;
    if (tid < E_*L_) cnt[tid] = 0;
    __syncthreads();
    for (int p = tid; p < P_; p += blockDim.x)
        atomicAdd(&cnt[topk_ids[p]*L_ + lora_idx[p>>1]], 1);
    __syncthreads();
    if (tid == 0) {
        int acc = 0;
        for (int b = 0; b < E_*L_; b++) {
            if ((b & (L_-1)) == 0) g_off[b/L_] = acc;
            cur[b] = acc; acc += cnt[b];
        }
        g_off[E_] = acc;
    }
    __syncthreads();
    for (int p = tid; p < P_; p += blockDim.x) {
        int key = topk_ids[p]*L_ + lora_idx[p>>1];
        int pos = atomicAdd(&cur[key], 1);
        g_list[pos] = p;
        g_pos[p]    = pos;
    }
}

// ============================================================
// conva
// ============================================================
__global__ __launch_bounds__(256) void k_conva(
    const float* __restrict__ gu_a, const float* __restrict__ d_a) {
    int bid = blockIdx.x, tid = threadIdx.x;
    if (bid < 512) {
        size_t base = ((size_t)bid * 256 + tid) * 8;
        const float4* s = (const float4*)(gu_a + base);
        *(uint4*)(g_GAh + base) = cvt8(s[0], s[1]);
    } else {
        size_t base = ((size_t)(bid - 512) * 256 + tid) * 8;
        const float4* s = (const float4*)(d_a + base);
        *(uint4*)(g_DAh + base) = cvt8(s[0], s[1]);
    }
}

// ============================================================
// prep1: 4 sorted pairs per block
// ============================================================
__global__ __launch_bounds__(256) void k_prep1(
    const float* __restrict__ x,
    const int* __restrict__ topk_ids, const int* __restrict__ lora_idx) {
    __shared__ float sx[4][2048];
    __shared__ int sle[4], sp[4];
    int tid = threadIdx.x;
    int s0 = blockIdx.x * 4;
    if (tid < 4) {
        int p = g_list[s0 + tid];
        sp[tid] = p;
        sle[tid] = lora_idx[p >> 1] * E_ + topk_ids[p];
    }
    __syncthreads();
    #pragma unroll
    for (int j = 0; j < 4; j++) {
        int p = sp[j], t = p >> 1;
        const float4* x4 = (const float4*)(x + (size_t)t * H_);
        float4 v0 = x4[tid*2], v1 = x4[tid*2+1];
        *(float4*)&sx[j][tid*8]     = v0;
        *(float4*)&sx[j][tid*8 + 4] = v1;
        if ((p & 1) == 0)
            *(uint4*)(g_Xh + (size_t)t * H_ + tid*8) = cvt8(v0, v1);
    }
    {
        int j = tid >> 6, c = tid & 63;
        g_U1[(size_t)(s0 + j) * 64 + c] = __float2half(0.f);
    }
    __syncthreads();

    int lane = tid & 31, w = tid >> 5;
    bool uni = (sle[0] == sle[1]) && (sle[1] == sle[2]) && (sle[2] == sle[3]);
    if (uni) {
        const __half2* ga = (const __half2*)(g_GAh + ((size_t)sle[0]*R_ + w) * H_);
        const __half2* gb = ga + 8 * (H_/2);
        float sa[4] = {0,0,0,0}, sb[4] = {0,0,0,0};
        for (int it = lane; it < H_/2; it += 32) {
            float2 a2 = __half22float2(ga[it]);
            float2 b2 = __half22float2(gb[it]);
            #pragma unroll
            for (int j = 0; j < 4; j++) {
                float x0 = sx[j][2*it], x1 = sx[j][2*it + 1];
                sa[j] += x0*a2.x + x1*a2.y;
                sb[j] += x0*b2.x + x1*b2.y;
            }
        }
        #pragma unroll
        for (int j = 0; j < 4; j++) {
            float ra = wred(sa[j]), rb = wred(sb[j]);
            if (lane == 0) {
                int l = sle[j] / E_;
                __half* ru = g_U1 + (size_t)(s0 + j) * 64;
                ru[l*R_ + w]     = __float2half(ra);
                ru[l*R_ + w + 8] = __float2half(rb);
            }
        }
    } else {
        for (int j = 0; j < 4; j++) {
            const __half2* ga = (const __half2*)(g_GAh + ((size_t)sle[j]*R_ + w) * H_);
            const __half2* gb = ga + 8 * (H_/2);
            float sa = 0.f, sb = 0.f;
            for (int it = lane; it < H_/2; it += 32) {
                float2 a2 = __half22float2(ga[it]);
                float2 b2 = __half22float2(gb[it]);
                float x0 = sx[j][2*it], x1 = sx[j][2*it + 1];
                sa += x0*a2.x + x1*a2.y;
                sb += x0*b2.x + x1*b2.y;
            }
            sa = wred(sa); sb = wred(sb);
            if (lane == 0) {
                int l = sle[j] / E_;
                __half* ru = g_U1 + (size_t)(s0 + j) * 64;
                ru[l*R_ + w]     = __float2half(sa);
                ru[l*R_ + w + 8] = __float2half(sb);
            }
        }
    }
}

// ============================================================
// weight conversion
// ============================================================
__global__ __launch_bounds__(256) void k_convw1(
    const float* __restrict__ w13, const float* __restrict__ gu_b, int ebase) {
    int rc = ebase * I2_ + blockIdx.x;
    int tid = threadIdx.x;
    int e = rc >> 11, c = rc & 2047;
    const float4* src = (const float4*)(w13 + (size_t)rc * H_);
    __half* bh = g_B1 + (size_t)rc * KT1;
    *(uint4*)(bh + tid*8) = cvt8(src[tid*2], src[tid*2+1]);
    if (tid < L_*R_) {
        int l = tid >> 4, r = tid & 15;
        bh[H_+tid] = __float2half(gu_b[(((size_t)l*E_ + e)*I2_ + c)*R_ + r]);
    }
}

__global__ __launch_bounds__(256) void k_convw2(
    const float* __restrict__ w2, const float* __restrict__ d_b) {
    int rc = blockIdx.x, tid = threadIdx.x;
    int e = rc >> 11, c = rc & 2047;
    const float4* src = (const float4*)(w2 + (size_t)rc * I_);
    __half* bh = g_B2 + (size_t)rc * KT2;
    float4 v0 = src[tid];
    *(uint2*)(bh + tid*4) = make_uint2(
        pk2(__float2half(v0.x), __float2half(v0.y)),
        pk2(__float2half(v0.z), __float2half(v0.w)));
    if (tid < L_*R_) {
        int l = tid >> 4, r = tid & 15;
        bh[I_+tid] = __float2half(d_b[(((size_t)l*E_ + e)*H_ + c)*R_ + r]);
    }
}

// ============================================================
// prep2: 4 pairs per block
// ============================================================
__global__ __launch_bounds__(256) void k_prep2(
    const int* __restrict__ topk_ids, const int* __restrict__ lora_idx) {
    __shared__ __half2 sac[4][512];
    __shared__ int sle[4];
    int tid = threadIdx.x;
    int s0 = blockIdx.x * 4;
    if (tid < 4) {
        int p = g_list[s0 + tid];
        sle[tid] = lora_idx[p >> 1] * E_ + topk_ids[p];
    }
    __syncthreads();
    #pragma unroll
    for (int j = 0; j < 4; j += 2) {
        int row = j + (tid >> 7);
        int c   = tid & 127;
        const uint4 v = *(const uint4*)(g_A2 + (size_t)(s0 + row) * KT2 + c*8);
        *(uint4*)&sac[row][c*4] = v;
    }
    {
        int j = tid >> 6, c = tid & 63;
        g_A2[(size_t)(s0 + j) * KT2 + I_ + c] = __float2half(0.f);
    }
    __syncthreads();

    int lane = tid & 31, w = tid >> 5;
    bool uni = (sle[0] == sle[1]) && (sle[1] == sle[2]) && (sle[2] == sle[3]);
    if (uni) {
        const __half2* ga = (const __half2*)(g_DAh + ((size_t)sle[0]*R_ + w) * I_);
        const __half2* gb = ga + 8 * (I_/2);
        float sa[4] = {0,0,0,0}, sb[4] = {0,0,0,0};
        for (int it = lane; it < I_/2; it += 32) {
            float2 a2 = __half22float2(ga[it]);
            float2 b2 = __half22float2(gb[it]);
            #pragma unroll
            for (int j = 0; j < 4; j++) {
                float2 xv = __half22float2(sac[j][it]);
                sa[j] += xv.x*a2.x + xv.y*a2.y;
                sb[j] += xv.x*b2.x + xv.y*b2.y;
            }
        }
        #pragma unroll
        for (int j = 0; j < 4; j++) {
            float ra = wred(sa[j]), rb = wred(sb[j]);
            if (lane == 0) {
                int l = sle[j] / E_;
                __half* ru = g_A2 + (size_t)(s0 + j) * KT2 + I_;
                ru[l*R_ + w]     = __float2half(ra);
                ru[l*R_ + w + 8] = __float2half(rb);
            }
        }
    } else {
        for (int j = 0; j < 4; j++) {
            const __half2* ga = (const __half2*)(g_DAh + ((size_t)sle[j]*R_ + w) * I_);
            const __half2* gb = ga + 8 * (I_/2);
            float sa = 0.f, sb = 0.f;
            for (int it = lane; it < I_/2; it += 32) {
                float2 a2 = __half22float2(ga[it]);
                float2 b2 = __half22float2(gb[it]);
                float2 xv = __half22float2(sac[j][it]);
                sa += xv.x*a2.x + xv.y*a2.y;
                sb += xv.x*b2.x + xv.y*b2.y;
            }
            sa = wred(sa); sb = wred(sb);
            if (lane == 0) {
                int l = sle[j] / E_;
                __half* ru = g_A2 + (size_t)(s0 + j) * KT2 + I_;
                ru[l*R_ + w]     = __float2half(sa);
                ru[l*R_ + w + 8] = __float2half(sb);
            }
        }
    }
}

// ============================================================
// mma.sync GEMM: CTA 128x128, 256 threads / 8 warps (4x2, warp 32x64),
// K chunk 64, 3 stages x 32KB = 96KB -> 2 CTAs/SM.
// GEMM1: N = 64 gate + 64 up cols; SwiGLU*cw epilogue -> A2 fp16.
// GEMM2: N = 128 H cols -> g_Dh fp16.
// ============================================================
#define STAGE 32768
#define SMEMB (3*STAGE)   // 98304 >= exchange 128*132*4 = 67584

template<int GEMM>
__global__ __launch_bounds__(256, 2) void k_gemm_mma(const float* __restrict__ tw, int ezoff) {
    constexpr int KTOT = (GEMM == 1) ? KT1 : KT2;
    constexpr int NK   = KTOT / 64;
    constexpr int NKX  = NK - 1;
    const __half* Bb = (GEMM == 1) ? g_B1 : g_B2;

    int e   = blockIdx.z + ezoff;
    int off = g_off[e];
    int cnt = g_off[e+1] - off;
    int m0  = blockIdx.y * 128;
    if (m0 >= cnt) return;

    extern __shared__ char smem_raw[];
    uint32_t sbase = smem_u32(smem_raw);

    int tid = threadIdx.x;
    int lane = tid & 31, wid = tid >> 5;
    int wm = wid >> 1, wn = wid & 1;   // 4x2 warp grid, 32x64 each

    // ---- loader bases: r0 = tid>>3 in [0,32), rows r0+32j; c = tid&7 ----
    int r0 = tid >> 3, c8 = tid & 7;
    uint32_t sA0 = swz64(r0, c8);          // +4096*j for row r0+32j
    uint32_t aX[4], aU[4];
    #pragma unroll
    for (int j = 0; j < 4; j++) {
        int rA = m0 + r0 + 32*j; if (rA > cnt-1) rA = cnt-1;
        int srow = off + rA;
        if (GEMM == 1) {
            int p = g_list[srow];
            aX[j] = (uint32_t)(p >> 1) * H_ + c8*8;
            aU[j] = (uint32_t)srow * 64 + c8*8;
        } else {
            aX[j] = (uint32_t)srow * KT2 + c8*8;
        }
    }
    uint32_t bO[4];
    #pragma unroll
    for (int j = 0; j < 4; j++) {
        int n = r0 + 32*j;
        int colB;
        if (GEMM == 1) colB = blockIdx.x*64 + (n & 63) + ((n >> 6) * I_);
        else           colB = blockIdx.x*128 + n;
        bO[j] = ((uint32_t)e * 2048 + colB) * KTOT + c8*8;
    }

    auto issue = [&](int kt) {
        uint32_t st = sbase + (kt % 3) * STAGE;
        uint32_t kadd = (uint32_t)kt * 64;
        #pragma unroll
        for (int j = 0; j < 4; j++) {
            const __half* src;
            if (GEMM == 1) src = (kt < NKX) ? (g_Xh + aX[j] + kadd) : (g_U1 + aU[j]);
            else           src = g_A2 + aX[j] + kadd;
            cp16(st + sA0 + 4096u*j, src);
        }
        #pragma unroll
        for (int j = 0; j < 4; j++)
            cp16(st + 16384 + sA0 + 4096u*j, Bb + bO[j] + kadd);
    };

    // ---- ldmatrix lane geometry ----
    int aRow[2], bRow[4];
    #pragma unroll
    for (int i = 0; i < 2; i++) aRow[i] = wm*32 + i*16 + (lane & 15);
    int aC = (lane >> 4) & 1;
    #pragma unroll
    for (int g = 0; g < 4; g++) bRow[g] = wn*64 + g*16 + (lane & 7) + ((lane & 16) ? 8 : 0);
    int bC = (lane >> 3) & 1;

    float acc[2][8][4];
    #pragma unroll
    for (int i = 0; i < 2; i++)
        #pragma unroll
        for (int j = 0; j < 8; j++)
            #pragma unroll
            for (int q = 0; q < 4; q++) acc[i][j][q] = 0.f;

    issue(0); CP_COMMIT();
    issue(1); CP_COMMIT();

    for (int kt = 0; kt < NK; kt++) {
        CP_WAIT1();
        __syncthreads();
        if (kt + 2 < NK) issue(kt + 2);
        CP_COMMIT();

        uint32_t st = sbase + (kt % 3) * STAGE;
        #pragma unroll
        for (int h = 0; h < 4; h++) {
            uint32_t ar[2][4], br[4][4];
            #pragma unroll
            for (int i = 0; i < 2; i++)
                ldsm4(ar[i], st + swz64(aRow[i], 2*h + aC));
            #pragma unroll
            for (int g = 0; g < 4; g++)
                ldsm4(br[g], st + 16384 + swz64(bRow[g], 2*h + bC));
            #pragma unroll
            for (int i = 0; i < 2; i++)
                #pragma unroll
                for (int j = 0; j < 8; j++)
                    mma_f16(acc[i][j], ar[i], &br[j>>1][(j&1)*2]);
        }
    }
    CP_WAIT0();
    __syncthreads();

    if constexpr (GEMM == 1) {
        float* ex = reinterpret_cast<float*>(smem_raw);   // [128][132] fp32 = 67584B
        #pragma unroll
        for (int i = 0; i < 2; i++)
            #pragma unroll
            for (int j = 0; j < 8; j++) {
                int rr = wm*32 + i*16 + (lane >> 2);
                int cc = wn*64 + j*8 + (lane & 3)*2;
                ex[rr*132 + cc]       = acc[i][j][0];
                ex[rr*132 + cc + 1]   = acc[i][j][1];
                ex[(rr+8)*132 + cc]   = acc[i][j][2];
                ex[(rr+8)*132 + cc+1] = acc[i][j][3];
            }
        __syncthreads();
        int m = tid >> 1, half = tid & 1;   // 32 act cols per thread
        if (m0 + m < cnt) {
            size_t srow = (size_t)(off + m0 + m);
            float cw = tw[g_list[srow]];
            __half* da = g_A2 + srow * KT2 + blockIdx.x*64 + half*32;
            const float* gr = ex + m*132 + half*32;
            #pragma unroll
            for (int q = 0; q < 4; q++) {
                uint32_t hw[4];
                #pragma unroll
                for (int u = 0; u < 4; u++) {
                    float g0 = gr[q*8 + u*2], g1 = gr[q*8 + u*2 + 1];
                    float u0 = gr[64 + q*8 + u*2], u1 = gr[64 + q*8 + u*2 + 1];
                    float a0 = cw * u0 * g0 / (1.f + expf(-g0));
                    float a1 = cw * u1 * g1 / (1.f + expf(-g1));
                    hw[u] = pk2(__float2half(a0), __float2half(a1));
                }
                *(uint4*)(da + q*8) = make_uint4(hw[0], hw[1], hw[2], hw[3]);
            }
        }
    } else {
        int c0 = blockIdx.x * 128;
        #pragma unroll
        for (int i = 0; i < 2; i++) {
            int rr = m0 + wm*32 + i*16 + (lane >> 2);
            #pragma unroll
            for (int j = 0; j < 8; j++) {
                int cc = c0 + wn*64 + j*8 + (lane & 3)*2;
                if (rr < cnt)
                    *(uint32_t*)(g_Dh + (size_t)(off + rr) * H_ + cc) =
                        pk2(__float2half(acc[i][j][0]), __float2half(acc[i][j][1]));
                if (rr + 8 < cnt)
                    *(uint32_t*)(g_Dh + (size_t)(off + rr + 8) * H_ + cc) =
                        pk2(__float2half(acc[i][j][2]), __float2half(acc[i][j][3]));
            }
        }
    }
}

// ============================================================
// combine
// ============================================================
__global__ __launch_bounds__(256) void k_combine(float* __restrict__ out) {
    int idx = blockIdx.x * 256 + threadIdx.x;
    int t = idx >> 8, q = idx & 255;
    const uint4 u0 = *(const uint4*)(g_Dh + (size_t)g_pos[2*t]   * H_ + q*8);
    const uint4 u1 = *(const uint4*)(g_Dh + (size_t)g_pos[2*t+1] * H_ + q*8);
    const __half2* h0 = (const __half2*)&u0;
    const __half2* h1 = (const __half2*)&u1;
    float4 o0, o1;
    {
        float2 a = __half22float2(h0[0]), b = __half22float2(h1[0]);
        o0.x = a.x + b.x; o0.y = a.y + b.y;
        a = __half22float2(h0[1]); b = __half22float2(h1[1]);
        o0.z = a.x + b.x; o0.w = a.y + b.y;
        a = __half22float2(h0[2]); b = __half22float2(h1[2]);
        o1.x = a.x + b.x; o1.y = a.y + b.y;
        a = __half22float2(h0[3]); b = __half22float2(h1[3]);
        o1.z = a.x + b.x; o1.w = a.y + b.y;
    }
    float4* dst = (float4*)(out + (size_t)t * H_ + q*8);
    dst[0] = o0; dst[1] = o1;
}

// ============================================================
extern "C" void kernel_launch(void* const* d_in, const int* in_sizes, int n_in,
                              void* d_out, int out_size) {
    const float* x    = (const float*)d_in[0];
    const float* tw   = (const float*)d_in[1];
    const float* w13  = (const float*)d_in[2];
    const float* w2   = (const float*)d_in[3];
    const float* gu_a = (const float*)d_in[4];
    const float* gu_b = (const float*)d_in[5];
    const float* da   = (const float*)d_in[6];
    const float* db   = (const float*)d_in[7];
    const int*   ids  = (const int*)d_in[8];
    const int*   lidx = (const int*)d_in[9];
    float* out = (float*)d_out;

    static cudaStream_t s1 = nullptr;
    static cudaEvent_t evFork = nullptr, evA = nullptr;
    static cudaEvent_t evW1a = nullptr, evW1b = nullptr, evW2 = nullptr;
    if (!s1) {
        cudaStreamCreate(&s1);
        cudaEventCreateWithFlags(&evFork, cudaEventDisableTiming);
        cudaEventCreateWithFlags(&evA,    cudaEventDisableTiming);
        cudaEventCreateWithFlags(&evW1a,  cudaEventDisableTiming);
        cudaEventCreateWithFlags(&evW1b,  cudaEventDisableTiming);
        cudaEventCreateWithFlags(&evW2,   cudaEventDisableTiming);
        cudaFuncSetAttribute(k_gemm_mma<1>, cudaFuncAttributeMaxDynamicSharedMemorySize, SMEMB);
        cudaFuncSetAttribute(k_gemm_mma<2>, cudaFuncAttributeMaxDynamicSharedMemorySize, SMEMB);
    }

    // side stream: LoRA-A tables, then weight conversions (split convw1)
    cudaEventRecord(evFork, 0);
    cudaStreamWaitEvent(s1, evFork, 0);
    k_conva  <<<768, 256, 0, s1>>>(gu_a, da);
    cudaEventRecord(evA, s1);
    k_convw1 <<<4*I2_, 256, 0, s1>>>(w13, gu_b, 0);
    cudaEventRecord(evW1a, s1);
    k_convw1 <<<4*I2_, 256, 0, s1>>>(w13, gu_b, 4);
    cudaEventRecord(evW1b, s1);
    k_convw2 <<<E_*H_,  256, 0, s1>>>(w2, db);
    cudaEventRecord(evW2, s1);

    // main chain
    k_route  <<<1, 1024>>>(ids, lidx);
    cudaStreamWaitEvent(0, evA, 0);
    k_prep1  <<<P_/4, 256>>>(x, ids, lidx);
    cudaStreamWaitEvent(0, evW1a, 0);
    k_gemm_mma<1><<<dim3(16, 64, 4), 256, SMEMB>>>(tw, 0);
    cudaStreamWaitEvent(0, evW1b, 0);
    k_gemm_mma<1><<<dim3(16, 64, 4), 256, SMEMB>>>(tw, 4);
    k_prep2  <<<P_/4, 256>>>(ids, lidx);
    cudaStreamWaitEvent(0, evW2, 0);
    k_gemm_mma<2><<<dim3(16, 64, E_), 256, SMEMB>>>(tw, 0);
    k_combine<<<(T_*H_/8)/256, 256>>>(out);
}